// round 7
// baseline (speedup 1.0000x reference)
#include <cuda_runtime.h>

// Problem shape (fixed by the dataset): B=8, N=1024, C=128, H=W=512.
static constexpr int  Nc = 1024;
static constexpr int  C4 = 32;            // 128 floats = 32 float4 per pixel
static constexpr int  HW_SHIFT = 18;      // H*W = 2^18 pixels per batch image
static constexpr long long PIX = 8LL << HW_SHIFT;   // 2,097,152 pixels
static constexpr int  P = 4;              // pixels per warp (measured MLP sweet spot)

// Measured-optimal memory pattern (R2): one warp per 4 consecutive pixels,
// lane l owns float4-chunk l of each pixel's 128-float feature row.
//  - index load: lanes 0..3 load 4 consecutive int32 (one sector), shfl-bcast
//  - gather: 4 INDEPENDENT LDG.128 per thread (MLP=4), feat rows L1/L2-resident
//  - store: 4 coalesced 512B STG.128 bursts, streaming (__stcs): output is
//    write-once, evict-first keeps the 4MB feature table cache-resident.
// R3-R6 established: finer scheduling granularity -> higher DRAM utilization
// (P=8 / 512-thr / pipelined variants all 1-4us slower). This round probes the
// finest point on that axis: 128-thread CTAs (4 warps, 131072 blocks).
__global__ void __launch_bounds__(128)
convert2image_gather4f(const float4* __restrict__ feat,   // [B, N, C/4]
                       const int*    __restrict__ slic,   // [B*H*W]
                       float4*       __restrict__ out)    // [B*H*W, C/4]
{
    const long long warp_gid = (long long)blockIdx.x * (blockDim.x >> 5)
                             + (threadIdx.x >> 5);
    const long long pix0 = warp_gid * P;
    const int lane = threadIdx.x & 31;

    if (pix0 >= PIX) return;

    // All P pixels of a warp lie in the same batch image (P divides H*W).
    const int b = (int)(pix0 >> HW_SHIFT);
    const float4* __restrict__ fb = feat + ((long long)b * Nc) * C4;

    // Lanes 0..P-1 fetch the P segment labels (one 16B sector total).
    int myidx = 0;
    if (lane < P) myidx = __ldg(slic + pix0 + lane) - 1;   // labels 1-indexed

    float4 v[P];
    #pragma unroll
    for (int p = 0; p < P; p++) {
        const int idx = __shfl_sync(0xffffffffu, myidx, p);
        v[p] = make_float4(0.f, 0.f, 0.f, 0.f);
        if ((unsigned)idx < (unsigned)Nc) {
            v[p] = __ldg(fb + (long long)idx * C4 + lane);  // independent -> MLP=P
        }
    }

    float4* __restrict__ o = out + (pix0 << 5) + lane;
    #pragma unroll
    for (int p = 0; p < P; p++) {
        __stcs(o + (p << 5), v[p]);    // streaming: write-once, evict-first
    }
}

extern "C" void kernel_launch(void* const* d_in, const int* in_sizes, int n_in,
                              void* d_out, int out_size)
{
    const float4* feat = (const float4*)d_in[0];   // graph_lstm_output fp32 [B,N,C]
    const int*    slic = (const int*)d_in[1];      // slic_output int32 [B,H,W,1]
    float4*       out  = (float4*)d_out;           // fp32 [B,H,W,C]

    const int threads = 128;                        // 4 warps -> 16 pixels/block
    const long long pixels_per_block = (threads / 32) * P;
    const unsigned blocks = (unsigned)((PIX + pixels_per_block - 1) / pixels_per_block); // 131,072

    convert2image_gather4f<<<blocks, threads>>>(feat, slic, out);
}

// round 8
// speedup vs baseline: 1.0022x; 1.0022x over previous
#include <cuda_runtime.h>

// ============================================================================
// Convert2ImageLayer: out[b,h,w,:] = feat[b, slic[b,h,w]-1, :]  (0 if invalid)
// Shapes: B=8, N=1024, C=128, H=W=512.
//
// FINAL kernel — HBM-write-roofline reached.
//   compulsory traffic: 1.074 GB output writes (+12 MB reads) -> 134 us floor
//   measured: ~142 us = 7.6 TB/s effective = 95% of 8 TB/s spec
//
// Configuration (measured optimum over 7 rounds):
//   - one warp per P=4 consecutive pixels; lane l owns float4-chunk l of the
//     128-float feature row
//   - index load: lanes 0..3 read 4 consecutive int32 (one sector), shfl-bcast
//   - gather: 4 INDEPENDENT LDG.128 per thread (MLP=4; ptxas caps effective
//     MLP at ~4 — P=8 measured slower), feature table (4MB) is L2-resident
//   - store: 4 coalesced 512B STG.128 bursts with __stcs (write-once,
//     evict-first keeps feat resident in cache)
//   - fine granularity wins: 65536 small CTAs fill the per-SM L1tex wavefront
//     queues evenly across 148 SMs; coarser variants (P=8, 512-thr blocks,
//     software-pipelined strips) all measured 1-4 us slower.
// ============================================================================

static constexpr int  Nc = 1024;
static constexpr int  C4 = 32;            // 128 floats = 32 float4 per pixel
static constexpr int  HW_SHIFT = 18;      // H*W = 2^18 pixels per batch image
static constexpr long long PIX = 8LL << HW_SHIFT;   // 2,097,152 pixels
static constexpr int  P = 4;              // pixels per warp

__global__ void __launch_bounds__(256)
convert2image_gather4(const float4* __restrict__ feat,   // [B, N, C/4]
                      const int*    __restrict__ slic,   // [B*H*W]
                      float4*       __restrict__ out)    // [B*H*W, C/4]
{
    const long long warp_gid = (long long)blockIdx.x * (blockDim.x >> 5)
                             + (threadIdx.x >> 5);
    const long long pix0 = warp_gid * P;
    const int lane = threadIdx.x & 31;

    if (pix0 >= PIX) return;

    // All P pixels of a warp lie in the same batch image (P divides H*W).
    const int b = (int)(pix0 >> HW_SHIFT);
    const float4* __restrict__ fb = feat + ((long long)b * Nc) * C4;

    // Lanes 0..P-1 fetch the P segment labels (one 16B sector total).
    int myidx = 0;
    if (lane < P) myidx = __ldg(slic + pix0 + lane) - 1;   // labels 1-indexed

    float4 v[P];
    #pragma unroll
    for (int p = 0; p < P; p++) {
        const int idx = __shfl_sync(0xffffffffu, myidx, p);
        v[p] = make_float4(0.f, 0.f, 0.f, 0.f);
        if ((unsigned)idx < (unsigned)Nc) {
            v[p] = __ldg(fb + (long long)idx * C4 + lane);  // independent -> MLP=P
        }
    }

    float4* __restrict__ o = out + (pix0 << 5) + lane;
    #pragma unroll
    for (int p = 0; p < P; p++) {
        __stcs(o + (p << 5), v[p]);    // streaming: write-once, evict-first
    }
}

extern "C" void kernel_launch(void* const* d_in, const int* in_sizes, int n_in,
                              void* d_out, int out_size)
{
    const float4* feat = (const float4*)d_in[0];   // graph_lstm_output fp32 [B,N,C]
    const int*    slic = (const int*)d_in[1];      // slic_output int32 [B,H,W,1]
    float4*       out  = (float4*)d_out;           // fp32 [B,H,W,C]

    const int threads = 256;                        // 8 warps -> 32 pixels/block
    const long long pixels_per_block = (threads / 32) * P;
    const unsigned blocks = (unsigned)((PIX + pixels_per_block - 1) / pixels_per_block); // 65,536

    convert2image_gather4<<<blocks, threads>>>(feat, slic, out);
}